// round 14
// baseline (speedup 1.0000x reference)
#include <cuda_runtime.h>
#include <cuda_fp16.h>
#include <math.h>
#include <stdint.h>

#define BB 4
#define SS 1024
#define DD 1024
#define HH 16
#define DK 64
#define MM (BB * SS)   // 4096

// ---------------- scratch (device globals; no allocation allowed) -------------
__device__ uint32_t g_wqp[DD / 2 * DD];    // fp16 weights, k-pair packed [kp][n]
__device__ uint32_t g_wkp[DD / 2 * DD];
__device__ uint32_t g_wvt[DD * DD / 2];    // V weights TRANSPOSED [e][dp]
__device__ uint32_t g_wop[DD / 2 * DD];
__device__ float g_bqf[DD];
__device__ float g_bkf[DD];
__device__ float g_bvf[DD];
__device__ float g_wck[DD * HH];
__device__ float g_wcb[DD * HH];
__device__ float g_bck[HH];
__device__ float g_bcb[HH];
__device__ float g_qv[DK];
__device__ float g_bmean;
__device__ uint32_t g_aq[MM * DD / 2];     // fp16-packed query activations
__device__ uint32_t g_ak[MM * DD / 2];     // fp16-packed key activations
__device__ uint32_t g_avt[DD / 2 * MM];    // value TRANSPOSED fp16 d-pair packed [dp][row]
__device__ uint32_t g_qs[MM * DD / 2];     // Q proj (fp16 packed, pre-scaled by 1/8)
__device__ uint32_t g_k2[MM * DD / 2];     // K proj (fp16 packed)
__device__ uint32_t g_v2t[DD * MM / 2];    // V proj TRANSPOSED key-pair packed [e][kp]
__device__ uint32_t g_xp[MM * DD / 2];     // attention out (fp16 packed)
__device__ __half g_ckh[HH * MM];          // gate ck, head-major fp16 [h][key]
__device__ __half g_cbh[HH * MM];          // gate cb, head-major fp16 [h][key]
__device__ unsigned g_pm[BB * SS * SS / 32];

__device__ __forceinline__ uint32_t packh2(float a, float b) {
    __half2 h = __floats2half2_rn(a, b);
    return *(uint32_t*)&h;
}

#define MMA_F16(d, a, b) \
    asm volatile("mma.sync.aligned.m16n8k16.row.col.f32.f16.f16.f32 " \
                 "{%0,%1,%2,%3},{%4,%5,%6,%7},{%8,%9},{%0,%1,%2,%3};" \
                 : "+f"(d[0]), "+f"(d[1]), "+f"(d[2]), "+f"(d[3]) \
                 : "r"(a[0]), "r"(a[1]), "r"(a[2]), "r"(a[3]), "r"(b[0]), "r"(b[1]));

__device__ __forceinline__ void cpa16(void* dst, const void* src) {
    unsigned d = (unsigned)__cvta_generic_to_shared(dst);
    asm volatile("cp.async.cg.shared.global [%0], [%1], 16;\n" :: "r"(d), "l"(src));
}

// ---------------- 1. mega prep kernel ------------------------------------------
__global__ void __launch_bounds__(256)
mega_prep(const float* __restrict__ query, const float* __restrict__ key,
          const float* __restrict__ value, const int* __restrict__ mask,
          const float* __restrict__ wq, const float* __restrict__ bq,
          const float* __restrict__ wk, const float* __restrict__ bk,
          const float* __restrict__ wv, const float* __restrict__ bv,
          const float* __restrict__ wo,
          const float* __restrict__ sw, const float* __restrict__ sb,
          const float* __restrict__ qpw, const float* __restrict__ qpb,
          const float* __restrict__ kpw, const float* __restrict__ kpb,
          const float* __restrict__ vlw, const float* __restrict__ vlb,
          const float* __restrict__ chan_w, const float* __restrict__ chan_b) {
    __shared__ float ts[64][33];
    int bid = blockIdx.x;
    int tid = threadIdx.x;

    if (bid < 6144) {                       // fold projections
        int f = bid >> 11;
        int idx = (bid & 2047) * 256 + tid;
        int kp2 = idx >> 10;
        int n = idx & 1023;
        int h = n >> 6;
        int ep = n & 63;
        const float* W = (f == 0) ? wq : (f == 1) ? wk : wv;
        const float* P = (f == 0) ? sw : (f == 1) ? kpw : vlw;
        const float* w0 = W + (size_t)(2 * kp2) * DD + (h << 6);
        const float* w1 = w0 + DD;
        float s0 = 0.f, s1 = 0.f;
#pragma unroll 8
        for (int e = 0; e < DK; e++) {
            float pv = P[e * DK + ep];
            s0 = fmaf(w0[e], pv, s0);
            s1 = fmaf(w1[e], pv, s1);
        }
        uint32_t o = packh2(s0, s1);
        if (f == 0) g_wqp[idx] = o;
        else if (f == 1) g_wkp[idx] = o;
        else g_wvt[(size_t)n * (DD / 2) + kp2] = o;   // transposed [e][dp]
        return;
    }
    if (bid < 8192) {                       // wo pack
        int idx = (bid - 6144) * 256 + tid;
        int kp2 = idx >> 10;
        int n = idx & 1023;
        float s0 = __ldg(&wo[(size_t)(2 * kp2) * DD + n]);
        float s1 = __ldg(&wo[(size_t)(2 * kp2 + 1) * DD + n]);
        g_wop[idx] = packh2(s0, s1);
        return;
    }
    if (bid < 10240) {                      // mask pack
        int t = (bid - 8192) * 256 + tid;
        const int4* p = (const int4*)mask + (size_t)t * 2;
        int4 a = p[0], b = p[1];
        unsigned byte = (unsigned)(a.x != 0) | ((unsigned)(a.y != 0) << 1)
                      | ((unsigned)(a.z != 0) << 2) | ((unsigned)(a.w != 0) << 3)
                      | ((unsigned)(b.x != 0) << 4) | ((unsigned)(b.y != 0) << 5)
                      | ((unsigned)(b.z != 0) << 6) | ((unsigned)(b.w != 0) << 7);
        ((unsigned char*)g_pm)[t] = (unsigned char)byte;
        return;
    }
    if (bid < 18432) {                      // cvt query / key to fp16 pairs
        int isK = bid >= 14336;
        int i = (bid - (isK ? 14336 : 10240)) * 256 + tid;
        const float* in = isK ? key : query;
        uint32_t* out = isK ? g_ak : g_aq;
        float4 v = ((const float4*)in)[i];
        uint2 o;
        o.x = packh2(v.x, v.y);
        o.y = packh2(v.z, v.w);
        ((uint2*)out)[i] = o;
        return;
    }
    if (bid < 20480) {                      // value transpose -> g_avt [dp][row]
        int tb = bid - 18432;
        int rbase = (tb & 63) * 64;
        int dbase = (tb >> 6) * 32;
#pragma unroll
        for (int l = 0; l < 2; l++) {
            int lin = tid + l * 256;
            int r = lin >> 3;
            int c4 = (lin & 7) << 2;
            float4 v = *(const float4*)&value[(size_t)(rbase + r) * DD + dbase + c4];
            ts[r][c4] = v.x; ts[r][c4 + 1] = v.y;
            ts[r][c4 + 2] = v.z; ts[r][c4 + 3] = v.w;
        }
        __syncthreads();
#pragma unroll
        for (int l = 0; l < 4; l++) {
            int u = tid + l * 256;
            int row = u & 63;
            int dp = u >> 6;
            uint32_t w = packh2(ts[row][2 * dp], ts[row][2 * dp + 1]);
            g_avt[(size_t)((dbase >> 1) + dp) * MM + rbase + row] = w;
        }
        return;
    }
    // small precompute
    int T = (bid - 20480) * 256 + tid;
    if (T < 3072) {
        int f = T >> 10;
        int c = T & 1023;
        int h = c >> 6;
        int ep = c & 63;
        const float* b = (f == 0) ? bq : (f == 1) ? bk : bv;
        const float* P = (f == 0) ? sw : (f == 1) ? kpw : vlw;
        const float* pb = (f == 0) ? sb : (f == 1) ? kpb : vlb;
        float* O = (f == 0) ? g_bqf : (f == 1) ? g_bkf : g_bvf;
        float sum = pb[ep];
        for (int e = 0; e < DK; e++) sum += b[(h << 6) + e] * P[e * DK + ep];
        O[c] = sum;
        return;
    }
    T -= 3072;
    if (T < 16384) {
        int d = T >> 4, h = T & 15;
        float sum = 0.f;
        for (int e = 0; e < DK; e++) sum += wk[d * DD + (h << 6) + e] * chan_w[e];
        g_wck[d * HH + h] = sum;
        return;
    }
    T -= 16384;
    if (T < 16384) {
        int d = T >> 4, h = T & 15;
        float sum = 0.f;
        for (int e = 0; e < DK; e++) sum += wk[d * DD + (h << 6) + e] * chan_b[e];
        g_wcb[d * HH + h] = sum;
        return;
    }
    T -= 16384;
    if (T < 16) {
        float sum = 0.f;
        for (int e = 0; e < DK; e++) sum += bk[(T << 6) + e] * chan_w[e];
        g_bck[T] = sum;
        return;
    }
    T -= 16;
    if (T < 16) {
        float sum = 0.f;
        for (int e = 0; e < DK; e++) sum += bk[(T << 6) + e] * chan_b[e];
        g_bcb[T] = sum;
        return;
    }
    T -= 16;
    if (T < 64) {                           // qv scaled x8 (Q stored pre-scaled /8)
        float sum = 0.f;
        for (int ep = 0; ep < DK; ep++) sum += qpw[T * DK + ep];
        g_qv[T] = sum * 0.125f;
        return;
    }
    T -= 64;
    if (T == 0) {
        float sum = 0.f;
        for (int ep = 0; ep < DK; ep++) sum += qpb[ep];
        g_bmean = sum * (1.f / 64.f);
    }
}

// ---------------- 2. fp16 tensor-core GEMM -------------------------------------
// mode 0: f32 out. mode 2: elu+pack. mode 3: transposed-V. mode 4: elu,x1/8,pack.
#define GSTAGES 3
#define GBKP 16
#define ASTP 20
#define BSTP 136
#define ASZP (128 * ASTP)
#define BSZP (GBKP * BSTP)
#define GSM_BYTES (GSTAGES * (ASZP + BSZP) * 4)   // 56832

struct GemmArgs {
    const uint32_t* A[3];
    const uint32_t* B[3];
    const float* bias[3];
    void* C[3];
    int mode[3];
    int Nn[3];
};

__device__ __forceinline__ void gemm_load_stage(uint32_t* As, uint32_t* Bs,
                                                const uint32_t* A, const uint32_t* Bm,
                                                int brow, int bcol, int kt, int tid,
                                                int Nn) {
#pragma unroll
    for (int l = 0; l < 2; l++) {
        int lin = tid + l * 256;
        int row = lin >> 2, c4 = (lin & 3) << 2;
        cpa16(&As[row * ASTP + c4], &A[(size_t)(brow + row) * (DD / 2) + kt * GBKP + c4]);
    }
#pragma unroll
    for (int l = 0; l < 2; l++) {
        int lin = tid + l * 256;
        int kr = lin >> 5, c4 = (lin & 31) << 2;
        cpa16(&Bs[kr * BSTP + c4], &Bm[(size_t)(kt * GBKP + kr) * Nn + bcol + c4]);
    }
}

__global__ void __launch_bounds__(256, 2)
gemm_f16(GemmArgs ga) {
    extern __shared__ uint32_t smem_u[];
    uint32_t* Asm = smem_u;
    uint32_t* Bsm = smem_u + GSTAGES * ASZP;

    int z = blockIdx.z;
    const uint32_t* A = ga.A[z];
    const uint32_t* Bm = ga.B[z];
    const float* bias = ga.bias[z];
    int mode = ga.mode[z];
    int Nn = ga.Nn[z];

    int tid = threadIdx.x;
    int brow, bcol;
    if (mode == 3) { brow = blockIdx.x * 128; bcol = blockIdx.y * 128; }
    else           { brow = blockIdx.y * 128; bcol = blockIdx.x * 128; }
    int warp = tid >> 5;
    int lane = tid & 31;
    int gr = lane >> 2;
    int gc = lane & 3;
    int wrow = (warp >> 2) * 64;
    int wcol = (warp & 3) * 32;

    float acc[4][4][4];
#pragma unroll
    for (int mt = 0; mt < 4; mt++)
#pragma unroll
        for (int nt = 0; nt < 4; nt++)
#pragma unroll
            for (int r = 0; r < 4; r++) acc[mt][nt][r] = 0.f;

    const int KT = (DD / 2) / GBKP;   // 32
    gemm_load_stage(Asm, Bsm, A, Bm, brow, bcol, 0, tid, Nn);
    asm volatile("cp.async.commit_group;\n");
    gemm_load_stage(Asm + ASZP, Bsm + BSZP, A, Bm, brow, bcol, 1, tid, Nn);
    asm volatile("cp.async.commit_group;\n");

    int s0 = 0, s1 = 1, s2 = 2;
    for (int kt = 0; kt < KT; kt++) {
        asm volatile("cp.async.wait_group 1;\n" ::: "memory");
        __syncthreads();
        uint32_t* As = Asm + s0 * ASZP;
        uint32_t* Bs = Bsm + s0 * BSZP;
#pragma unroll
        for (int c2 = 0; c2 < 2; c2++) {
            int kpb = c2 * 8;
            uint32_t af[4][4], bf[4][2];
#pragma unroll
            for (int mt = 0; mt < 4; mt++) {
                int row0 = wrow + mt * 16 + gr;
                af[mt][0] = As[row0 * ASTP + kpb + gc];
                af[mt][1] = As[(row0 + 8) * ASTP + kpb + gc];
                af[mt][2] = As[row0 * ASTP + kpb + gc + 4];
                af[mt][3] = As[(row0 + 8) * ASTP + kpb + gc + 4];
            }
#pragma unroll
            for (int nt = 0; nt < 4; nt++) {
                int col0 = wcol + nt * 8 + gr;
                bf[nt][0] = Bs[(kpb + gc) * BSTP + col0];
                bf[nt][1] = Bs[(kpb + gc + 4) * BSTP + col0];
            }
#pragma unroll
            for (int mt = 0; mt < 4; mt++)
#pragma unroll
                for (int nt = 0; nt < 4; nt++)
                    MMA_F16(acc[mt][nt], af[mt], bf[nt]);
        }
        int nk = kt + 2;
        if (nk < KT)
            gemm_load_stage(Asm + s2 * ASZP, Bsm + s2 * BSZP, A, Bm, brow, bcol, nk, tid, Nn);
        asm volatile("cp.async.commit_group;\n");
        int t = s0; s0 = s1; s1 = s2; s2 = t;
    }

    // epilogue
#pragma unroll
    for (int mt = 0; mt < 4; mt++) {
        int r0 = brow + wrow + mt * 16 + gr;
#pragma unroll
        for (int nt = 0; nt < 4; nt++) {
            int c0 = bcol + wcol + nt * 8 + (gc << 1);
            float v0, v1, v2, v3;
            if (mode == 3) {
                float rb0 = bias[r0], rb1 = bias[r0 + 8];
                v0 = acc[mt][nt][0] + rb0;
                v1 = acc[mt][nt][1] + rb0;
                v2 = acc[mt][nt][2] + rb1;
                v3 = acc[mt][nt][3] + rb1;
            } else {
                float b0 = bias[c0], b1 = bias[c0 + 1];
                v0 = acc[mt][nt][0] + b0;
                v1 = acc[mt][nt][1] + b1;
                v2 = acc[mt][nt][2] + b0;
                v3 = acc[mt][nt][3] + b1;
            }
            if (mode >= 2) {
                v0 = v0 > 0.f ? v0 : (__expf(v0) - 1.f);
                v1 = v1 > 0.f ? v1 : (__expf(v1) - 1.f);
                v2 = v2 > 0.f ? v2 : (__expf(v2) - 1.f);
                v3 = v3 > 0.f ? v3 : (__expf(v3) - 1.f);
            }
            if (mode == 4) {
                v0 *= 0.125f; v1 *= 0.125f; v2 *= 0.125f; v3 *= 0.125f;
            }
            if (mode == 3) {
                uint32_t* Cw = (uint32_t*)ga.C[z];
                Cw[(size_t)r0 * (MM / 2) + (c0 >> 1)] = packh2(v0, v1);
                Cw[(size_t)(r0 + 8) * (MM / 2) + (c0 >> 1)] = packh2(v2, v3);
            } else if (mode >= 2) {
                uint32_t* Cw = (uint32_t*)ga.C[z];
                Cw[(size_t)r0 * (DD / 2) + (c0 >> 1)] = packh2(v0, v1);
                Cw[(size_t)(r0 + 8) * (DD / 2) + (c0 >> 1)] = packh2(v2, v3);
            } else {
                float* Cf = (float*)ga.C[z];
                *(float2*)&Cf[(size_t)r0 * DD + c0] = make_float2(v0, v1);
                *(float2*)&Cf[(size_t)(r0 + 8) * DD + c0] = make_float2(v2, v3);
            }
        }
    }
}

// ---------------- 3. ck/cb skinny GEMV (writes fp16 head-major) -----------------
__global__ void ckcb_kernel(const float* __restrict__ key) {
    __shared__ float rows[8][1024];
    int tid = threadIdx.x;
    int row0 = blockIdx.x * 8;
#pragma unroll
    for (int l = 0; l < 8; l++) {
        int lin = tid + l * 256;
        int r = lin >> 8;
        int c4 = (lin & 255) << 2;
        *(float4*)&rows[r][c4] = *(const float4*)&key[(size_t)(row0 + r) * DD + c4];
    }
    __syncthreads();
    int r = tid >> 5;
    int o = tid & 31;
    int h = o & 15;
    int isB = o >> 4;
    const float* wp = isB ? g_wcb : g_wck;
    float sum = isB ? g_bcb[h] : g_bck[h];
#pragma unroll 8
    for (int d = 0; d < DD; d++) sum += rows[r][d] * wp[d * HH + h];
    (isB ? g_cbh : g_ckh)[(size_t)h * MM + row0 + r] = __float2half(sum);
}

// ---------------- 4. flash attention: fixed-shift fp16 softmax, occ 3 ----------
// CTA: 64 q-rows x (b,h). 4 warps x 16 q-rows. K-tiles of 64, 2-buffer cp.async.
// No online max: scores are tiny (|s| << 10), softmax shift-invariant -> shift 0.
// exp + gate + mask all in f16x2; row sums accumulate per-thread, reduced once.
#define AKS 36
#define TILE_U (64 * AKS)
#define ASM_BYTES ((6 * TILE_U + 128) * 4)   // 55808

__global__ void __launch_bounds__(128, 3) attn_tc_kernel() {
    extern __shared__ uint32_t smu[];
    uint32_t* PsH = smu;                    // P [q][kp]
    uint32_t* Qh  = smu + TILE_U;           // Q [q][ep]
    uint32_t* KsB = smu + 2 * TILE_U;       // 2 x K [key][ep]
    uint32_t* VtB = smu + 4 * TILE_U;       // 2 x V^T [e][kp]
    uint32_t* ckB = smu + 6 * TILE_U;       // 2 x 32 u32 (64 fp16 ck)
    uint32_t* cbB = ckB + 64;               // 2 x 32 u32 (64 fp16 cb)

    int tid = threadIdx.x;
    int q0 = blockIdx.x * 64;
    int h = blockIdx.y;
    int b = blockIdx.z;
    int warp = tid >> 5;
    int lane = tid & 31;
    int gr = lane >> 2;
    int gc = lane & 3;
    int wrow = warp * 16;

    // issue Q staging (group 0)
#pragma unroll
    for (int l = 0; l < 4; l++) {
        int lin = tid + l * 128;
        int r = lin >> 3;
        int c4 = (lin & 7) << 2;
        cpa16(&Qh[r * AKS + c4],
              &g_qs[(size_t)((b << 10) + q0 + r) * (DD / 2) + (h << 5) + c4]);
    }
    asm volatile("cp.async.commit_group;\n");

    auto issue_tile = [&](int kt, int buf) {
        int k0 = kt * 64;
        uint32_t* Ks = KsB + buf * TILE_U;
        uint32_t* Vt = VtB + buf * TILE_U;
#pragma unroll
        for (int l = 0; l < 4; l++) {
            int lin = tid + l * 128;
            int r = lin >> 3;
            int c4 = (lin & 7) << 2;
            cpa16(&Ks[r * AKS + c4],
                  &g_k2[(size_t)((b << 10) + k0 + r) * (DD / 2) + (h << 5) + c4]);
            cpa16(&Vt[r * AKS + c4],
                  &g_v2t[(size_t)((h << 6) + r) * (MM / 2) + (((b << 10) + k0) >> 1) + c4]);
        }
        if (tid < 8)
            cpa16(&ckB[buf * 32 + tid * 4], &g_ckh[(size_t)h * MM + (b << 10) + k0 + tid * 8]);
        else if (tid < 16)
            cpa16(&cbB[buf * 32 + (tid - 8) * 4],
                  &g_cbh[(size_t)h * MM + (b << 10) + k0 + (tid - 8) * 8]);
        asm volatile("cp.async.commit_group;\n");
    };
    issue_tile(0, 0);

    asm volatile("cp.async.wait_group 1;\n" ::: "memory");
    __syncthreads();

    // Q fragments
    uint32_t qf[4][4];
#pragma unroll
    for (int c = 0; c < 4; c++) {
        qf[c][0] = Qh[(wrow + gr) * AKS + c * 8 + gc];
        qf[c][1] = Qh[(wrow + gr + 8) * AKS + c * 8 + gc];
        qf[c][2] = Qh[(wrow + gr) * AKS + c * 8 + gc + 4];
        qf[c][3] = Qh[(wrow + gr + 8) * AKS + c * 8 + gc + 4];
    }
    // inline per-row gate scalar m = Q_row . qv + bmean  (qv pre-scaled x8)
    const __half* q0h = (const __half*)(Qh + (wrow + gr) * AKS);
    const __half* q1h = (const __half*)(Qh + (wrow + gr + 8) * AKS);
    float a0 = 0.f, a1 = 0.f;
#pragma unroll
    for (int e16 = 0; e16 < 16; e16++) {
        int e = gc * 16 + e16;
        float qv = __ldg(&g_qv[e]);
        a0 = fmaf(__half2float(q0h[e]), qv, a0);
        a1 = fmaf(__half2float(q1h[e]), qv, a1);
    }
#pragma unroll
    for (int d = 1; d < 4; d <<= 1) {
        a0 += __shfl_xor_sync(0xffffffffu, a0, d);
        a1 += __shfl_xor_sync(0xffffffffu, a1, d);
    }
    float bmean = g_bmean;
    __half2 mq0h2 = __float2half2_rn(a0 + bmean);
    __half2 mq1h2 = __float2half2_rn(a1 + bmean);
    const __half2 nlog2e = __float2half2_rn(-1.44269504f);
    const __half2 plog2e = __float2half2_rn(1.44269504f);
    const __half2 oneh2 = __float2half2_rn(1.f);

    int qrow0 = q0 + wrow + gr;
    int qrow1 = qrow0 + 8;
    float rs0 = 0.f, rs1 = 0.f;     // per-thread partial row sums (reduced at end)
    float ofr[8][4];
#pragma unroll
    for (int nf = 0; nf < 8; nf++)
#pragma unroll
        for (int r = 0; r < 4; r++) ofr[nf][r] = 0.f;

    unsigned pmbase0 = ((unsigned)((b << 10) + qrow0)) << 5;
    unsigned pmbase1 = ((unsigned)((b << 10) + qrow1)) << 5;

    for (int kt = 0; kt < 16; kt++) {
        int cur = kt & 1;
        __syncthreads();
        if (kt < 15) issue_tile(kt + 1, 1 - cur);
        if (kt < 15) { asm volatile("cp.async.wait_group 1;\n" ::: "memory"); }
        else         { asm volatile("cp.async.wait_group 0;\n" ::: "memory"); }
        __syncthreads();

        uint32_t* Ks = KsB + cur * TILE_U;
        uint32_t* Vt = VtB + cur * TILE_U;
        const __half2* ckh = (const __half2*)(ckB + cur * 32);
        const __half2* cbh = (const __half2*)(cbB + cur * 32);
        int k0 = kt * 64;

        // ---- scores S = Q @ K^T (fp16; Q pre-scaled by 1/8) ----
        float sfr[8][4];
#pragma unroll
        for (int nf = 0; nf < 8; nf++)
#pragma unroll
            for (int r = 0; r < 4; r++) sfr[nf][r] = 0.f;
#pragma unroll
        for (int c = 0; c < 4; c++) {
#pragma unroll
            for (int nf = 0; nf < 8; nf++) {
                uint32_t bf[2];
                bf[0] = Ks[(nf * 8 + gr) * AKS + c * 8 + gc];
                bf[1] = Ks[(nf * 8 + gr) * AKS + c * 8 + gc + 4];
                MMA_F16(sfr[nf], qf[c], bf);
            }
        }

        // ---- gate + exp (all f16x2, fixed shift 0) + mask + P store + sums ----
        unsigned w00 = g_pm[pmbase0 + (k0 >> 5)];
        unsigned w01 = g_pm[pmbase0 + (k0 >> 5) + 1];
        unsigned w10 = g_pm[pmbase1 + (k0 >> 5)];
        unsigned w11 = g_pm[pmbase1 + (k0 >> 5) + 1];
#pragma unroll
        for (int nf = 0; nf < 8; nf++) {
            int c0 = nf * 8 + (gc << 1);     // even; c0 and c0+1 share a pm word
            __half2 ckp = ckh[nf * 4 + gc];
            __half2 cbp = cbh[nf * 4 + gc];
            // gate = sigmoid(m*ck + cb); fold log2e into gate for the exp2 below
            __half2 l0 = __hfma2(mq0h2, ckp, cbp);
            __half2 l1 = __hfma2(mq1h2, ckp, cbp);
            __half2 g0 = __hmul2(h2rcp(__hadd2(oneh2, h2exp2(__hmul2(l0, nlog2e)))), plog2e);
            __half2 g1 = __hmul2(h2rcp(__hadd2(oneh2, h2exp2(__hmul2(l1, nlog2e)))), plog2e);
            // p = exp2(s * g*log2e)
            __half2 s0h = __floats2half2_rn(sfr[nf][0], sfr[nf][1]);
            __half2 s1h = __floats2half2_rn(sfr[nf][2], sfr[nf][3]);
            __half2 p0 = h2exp2(__hmul2(s0h, g0));
            __half2 p1 = h2exp2(__hmul2(s1h, g1));
            // mask: 2 bits -> half2 {0,1} multiplier
            unsigned bits0 = ((c0 < 32) ? w00 : w01) >> (c0 & 31);
            unsigned bits1 = ((c0 < 32) ? w10 : w11) >> (c0 & 31);
            unsigned mm0 = (bits0 & 1u) * 0x3C00u | ((bits0 >> 1) & 1u) * 0x3C000000u;
            unsigned mm1 = (bits1 & 1u) * 0x3C00u | ((bits1 >> 1) & 1u) * 0x3C000000u;
            p0 = __hmul2(p0, *(__half2*)&mm0);
            p1 = __hmul2(p1, *(__half2*)&mm1);
            // P store (already fp16-packed key pairs)
            int kp = nf * 4 + gc;
            PsH[(wrow + gr) * AKS + kp] = *(uint32_t*)&p0;
            PsH[(wrow + gr + 8) * AKS + kp] = *(uint32_t*)&p1;
            // accumulate row sums (same fp16 p as PV MMA -> consistent)
            float2 pf0 = __half22float2(p0);
            float2 pf1 = __half22float2(p1);
            rs0 += pf0.x + pf0.y;
            rs1 += pf1.x + pf1.y;
        }
        __syncwarp();

        // ---- O += P @ V (fp16; V^T [e][kp]) ----
#pragma unroll
        for (int c = 0; c < 4; c++) {
            uint32_t af[4];
            af[0] = PsH[(wrow + gr) * AKS + c * 8 + gc];
            af[1] = PsH[(wrow + gr + 8) * AKS + c * 8 + gc];
            af[2] = PsH[(wrow + gr) * AKS + c * 8 + gc + 4];
            af[3] = PsH[(wrow + gr + 8) * AKS + c * 8 + gc + 4];
#pragma unroll
            for (int nf = 0; nf < 8; nf++) {
                uint32_t bf[2];
                bf[0] = Vt[(nf * 8 + gr) * AKS + c * 8 + gc];
                bf[1] = Vt[(nf * 8 + gr) * AKS + c * 8 + gc + 4];
                MMA_F16(ofr[nf], af, bf);
            }
        }
    }

    // ---- single final row-sum reduction + normalize + write ----
#pragma unroll
    for (int d = 1; d < 4; d <<= 1) {
        rs0 += __shfl_xor_sync(0xffffffffu, rs0, d);
        rs1 += __shfl_xor_sync(0xffffffffu, rs1, d);
    }
    float inv0 = 1.f / rs0;
    float inv1 = 1.f / rs1;
#pragma unroll
    for (int nf = 0; nf < 8; nf++) {
        int c0 = (h << 6) + nf * 8 + (gc << 1);
        g_xp[(size_t)((b << 10) + qrow0) * (DD / 2) + (c0 >> 1)] =
            packh2(ofr[nf][0] * inv0, ofr[nf][1] * inv0);
        g_xp[(size_t)((b << 10) + qrow1) * (DD / 2) + (c0 >> 1)] =
            packh2(ofr[nf][2] * inv1, ofr[nf][3] * inv1);
    }
}

// ---------------- launch --------------------------------------------------------
extern "C" void kernel_launch(void* const* d_in, const int* in_sizes, int n_in,
                              void* d_out, int out_size) {
    const float* query = (const float*)d_in[0];
    const float* key   = (const float*)d_in[1];
    const float* value = (const float*)d_in[2];
    const int*   mask  = (const int*)d_in[3];
    const float* wq = (const float*)d_in[4];
    const float* bq = (const float*)d_in[5];
    const float* wk = (const float*)d_in[6];
    const float* bk = (const float*)d_in[7];
    const float* wv = (const float*)d_in[8];
    const float* bv = (const float*)d_in[9];
    const float* wo = (const float*)d_in[10];
    const float* bo = (const float*)d_in[11];
    const float* spatial_w = (const float*)d_in[12];
    const float* spatial_b = (const float*)d_in[13];
    const float* qproj_w = (const float*)d_in[14];
    const float* qproj_b = (const float*)d_in[15];
    const float* kproj_w = (const float*)d_in[16];
    const float* kproj_b = (const float*)d_in[17];
    const float* vlin_w = (const float*)d_in[18];
    const float* vlin_b = (const float*)d_in[19];
    const float* chan_w = (const float*)d_in[20];
    const float* chan_b = (const float*)d_in[21];
    float* out = (float*)d_out;

    float *p_bqf, *p_bkf, *p_bvf;
    uint32_t *p_wqp, *p_wkp, *p_wvt, *p_wop, *p_aq, *p_ak, *p_avt;
    uint32_t *p_qs, *p_k2, *p_v2t, *p_xp;
    cudaGetSymbolAddress((void**)&p_bqf, g_bqf);
    cudaGetSymbolAddress((void**)&p_bkf, g_bkf);
    cudaGetSymbolAddress((void**)&p_bvf, g_bvf);
    cudaGetSymbolAddress((void**)&p_wqp, g_wqp);
    cudaGetSymbolAddress((void**)&p_wkp, g_wkp);
    cudaGetSymbolAddress((void**)&p_wvt, g_wvt);
    cudaGetSymbolAddress((void**)&p_wop, g_wop);
    cudaGetSymbolAddress((void**)&p_aq, g_aq);
    cudaGetSymbolAddress((void**)&p_ak, g_ak);
    cudaGetSymbolAddress((void**)&p_avt, g_avt);
    cudaGetSymbolAddress((void**)&p_qs, g_qs);
    cudaGetSymbolAddress((void**)&p_k2, g_k2);
    cudaGetSymbolAddress((void**)&p_v2t, g_v2t);
    cudaGetSymbolAddress((void**)&p_xp, g_xp);

    cudaFuncSetAttribute(gemm_f16, cudaFuncAttributeMaxDynamicSharedMemorySize, GSM_BYTES);
    cudaFuncSetAttribute(attn_tc_kernel, cudaFuncAttributeMaxDynamicSharedMemorySize, ASM_BYTES);

    // 1. all independent prep in one launch
    mega_prep<<<20621, 256>>>(query, key, value, mask,
                              wq, bq, wk, bk, wv, bv, wo,
                              spatial_w, spatial_b, qproj_w, qproj_b,
                              kproj_w, kproj_b, vlin_w, vlin_b, chan_w, chan_b);
    // 2. ck/cb gate scalars (fp16, head-major)
    ckcb_kernel<<<MM / 8, 256>>>(key);

    // 3. merged QKV fp16 GEMM: Q (elu, x1/8), K (elu), V transposed (elu)
    GemmArgs gqkv;
    gqkv.A[0] = p_aq;  gqkv.A[1] = p_ak;  gqkv.A[2] = p_wvt;
    gqkv.B[0] = p_wqp; gqkv.B[1] = p_wkp; gqkv.B[2] = p_avt;
    gqkv.bias[0] = p_bqf; gqkv.bias[1] = p_bkf; gqkv.bias[2] = p_bvf;
    gqkv.C[0] = p_qs;  gqkv.C[1] = p_k2;  gqkv.C[2] = p_v2t;
    gqkv.mode[0] = 4;  gqkv.mode[1] = 2;  gqkv.mode[2] = 3;
    gqkv.Nn[0] = DD;   gqkv.Nn[1] = DD;   gqkv.Nn[2] = MM;
    gemm_f16<<<dim3(8, 32, 3), 256, GSM_BYTES>>>(gqkv);

    // 4. attention: fixed-shift fp16 softmax (occ 3, cp.async)
    attn_tc_kernel<<<dim3(SS / 64, HH, BB), 128, ASM_BYTES>>>();

    // 5. fp16 output projection
    GemmArgs go;
    go.A[0] = go.A[1] = go.A[2] = p_xp;
    go.B[0] = go.B[1] = go.B[2] = p_wop;
    go.bias[0] = go.bias[1] = go.bias[2] = bo;
    go.C[0] = go.C[1] = go.C[2] = out;
    go.mode[0] = go.mode[1] = go.mode[2] = 0;
    go.Nn[0] = go.Nn[1] = go.Nn[2] = DD;
    gemm_f16<<<dim3(8, 32, 1), 256, GSM_BYTES>>>(go);
}

// round 15
// speedup vs baseline: 1.0269x; 1.0269x over previous
#include <cuda_runtime.h>
#include <cuda_fp16.h>
#include <math.h>
#include <stdint.h>

#define BB 4
#define SS 1024
#define DD 1024
#define HH 16
#define DK 64
#define MM (BB * SS)   // 4096

// ---------------- scratch (device globals; no allocation allowed) -------------
__device__ uint32_t g_wqp[DD / 2 * DD];    // fp16 weights, k-pair packed [kp][n]
__device__ uint32_t g_wkp[DD / 2 * DD];
__device__ uint32_t g_wvt[DD * DD / 2];    // V weights TRANSPOSED [e][dp]
__device__ uint32_t g_wop[DD / 2 * DD];
__device__ float g_bqf[DD];
__device__ float g_bkf[DD];
__device__ float g_bvf[DD];
__device__ float g_wck[DD * HH];
__device__ float g_wcb[DD * HH];
__device__ float g_bck[HH];
__device__ float g_bcb[HH];
__device__ float g_qv[DK];
__device__ float g_bmean;
__device__ uint32_t g_aq[MM * DD / 2];     // fp16-packed query activations
__device__ uint32_t g_ak[MM * DD / 2];     // fp16-packed key activations
__device__ uint32_t g_avt[DD / 2 * MM];    // value TRANSPOSED fp16 d-pair packed [dp][row]
__device__ uint32_t g_qs[MM * DD / 2];     // Q proj (fp16 packed, pre-scaled by 1/8)
__device__ uint32_t g_k2[MM * DD / 2];     // K proj (fp16 packed)
__device__ uint32_t g_v2t[DD * MM / 2];    // V proj TRANSPOSED key-pair packed [e][kp]
__device__ uint32_t g_xp[MM * DD / 2];     // attention out (fp16 packed)
__device__ __half g_ckh[HH * MM];          // gate ck, head-major fp16 [h][key]
__device__ __half g_cbh[HH * MM];          // gate cb, head-major fp16 [h][key]
__device__ unsigned g_pm[BB * SS * SS / 32];

__device__ __forceinline__ uint32_t packh2(float a, float b) {
    __half2 h = __floats2half2_rn(a, b);
    return *(uint32_t*)&h;
}

#define MMA_F16(d, a, b) \
    asm volatile("mma.sync.aligned.m16n8k16.row.col.f32.f16.f16.f32 " \
                 "{%0,%1,%2,%3},{%4,%5,%6,%7},{%8,%9},{%0,%1,%2,%3};" \
                 : "+f"(d[0]), "+f"(d[1]), "+f"(d[2]), "+f"(d[3]) \
                 : "r"(a[0]), "r"(a[1]), "r"(a[2]), "r"(a[3]), "r"(b[0]), "r"(b[1]));

__device__ __forceinline__ void cpa16(void* dst, const void* src) {
    unsigned d = (unsigned)__cvta_generic_to_shared(dst);
    asm volatile("cp.async.cg.shared.global [%0], [%1], 16;\n" :: "r"(d), "l"(src));
}

// ---------------- 1. mega prep kernel ------------------------------------------
__global__ void __launch_bounds__(256)
mega_prep(const float* __restrict__ query, const float* __restrict__ key,
          const float* __restrict__ value, const int* __restrict__ mask,
          const float* __restrict__ wq, const float* __restrict__ bq,
          const float* __restrict__ wk, const float* __restrict__ bk,
          const float* __restrict__ wv, const float* __restrict__ bv,
          const float* __restrict__ wo,
          const float* __restrict__ sw, const float* __restrict__ sb,
          const float* __restrict__ qpw, const float* __restrict__ qpb,
          const float* __restrict__ kpw, const float* __restrict__ kpb,
          const float* __restrict__ vlw, const float* __restrict__ vlb,
          const float* __restrict__ chan_w, const float* __restrict__ chan_b) {
    __shared__ float ts[64][33];
    int bid = blockIdx.x;
    int tid = threadIdx.x;

    if (bid < 6144) {                       // fold projections
        int f = bid >> 11;
        int idx = (bid & 2047) * 256 + tid;
        int kp2 = idx >> 10;
        int n = idx & 1023;
        int h = n >> 6;
        int ep = n & 63;
        const float* W = (f == 0) ? wq : (f == 1) ? wk : wv;
        const float* P = (f == 0) ? sw : (f == 1) ? kpw : vlw;
        const float* w0 = W + (size_t)(2 * kp2) * DD + (h << 6);
        const float* w1 = w0 + DD;
        float s0 = 0.f, s1 = 0.f;
#pragma unroll 8
        for (int e = 0; e < DK; e++) {
            float pv = P[e * DK + ep];
            s0 = fmaf(w0[e], pv, s0);
            s1 = fmaf(w1[e], pv, s1);
        }
        uint32_t o = packh2(s0, s1);
        if (f == 0) g_wqp[idx] = o;
        else if (f == 1) g_wkp[idx] = o;
        else g_wvt[(size_t)n * (DD / 2) + kp2] = o;   // transposed [e][dp]
        return;
    }
    if (bid < 8192) {                       // wo pack
        int idx = (bid - 6144) * 256 + tid;
        int kp2 = idx >> 10;
        int n = idx & 1023;
        float s0 = __ldg(&wo[(size_t)(2 * kp2) * DD + n]);
        float s1 = __ldg(&wo[(size_t)(2 * kp2 + 1) * DD + n]);
        g_wop[idx] = packh2(s0, s1);
        return;
    }
    if (bid < 10240) {                      // mask pack
        int t = (bid - 8192) * 256 + tid;
        const int4* p = (const int4*)mask + (size_t)t * 2;
        int4 a = p[0], b = p[1];
        unsigned byte = (unsigned)(a.x != 0) | ((unsigned)(a.y != 0) << 1)
                      | ((unsigned)(a.z != 0) << 2) | ((unsigned)(a.w != 0) << 3)
                      | ((unsigned)(b.x != 0) << 4) | ((unsigned)(b.y != 0) << 5)
                      | ((unsigned)(b.z != 0) << 6) | ((unsigned)(b.w != 0) << 7);
        ((unsigned char*)g_pm)[t] = (unsigned char)byte;
        return;
    }
    if (bid < 18432) {                      // cvt query / key to fp16 pairs
        int isK = bid >= 14336;
        int i = (bid - (isK ? 14336 : 10240)) * 256 + tid;
        const float* in = isK ? key : query;
        uint32_t* out = isK ? g_ak : g_aq;
        float4 v = ((const float4*)in)[i];
        uint2 o;
        o.x = packh2(v.x, v.y);
        o.y = packh2(v.z, v.w);
        ((uint2*)out)[i] = o;
        return;
    }
    if (bid < 20480) {                      // value transpose -> g_avt [dp][row]
        int tb = bid - 18432;
        int rbase = (tb & 63) * 64;
        int dbase = (tb >> 6) * 32;
#pragma unroll
        for (int l = 0; l < 2; l++) {
            int lin = tid + l * 256;
            int r = lin >> 3;
            int c4 = (lin & 7) << 2;
            float4 v = *(const float4*)&value[(size_t)(rbase + r) * DD + dbase + c4];
            ts[r][c4] = v.x; ts[r][c4 + 1] = v.y;
            ts[r][c4 + 2] = v.z; ts[r][c4 + 3] = v.w;
        }
        __syncthreads();
#pragma unroll
        for (int l = 0; l < 4; l++) {
            int u = tid + l * 256;
            int row = u & 63;
            int dp = u >> 6;
            uint32_t w = packh2(ts[row][2 * dp], ts[row][2 * dp + 1]);
            g_avt[(size_t)((dbase >> 1) + dp) * MM + rbase + row] = w;
        }
        return;
    }
    // small precompute
    int T = (bid - 20480) * 256 + tid;
    if (T < 3072) {
        int f = T >> 10;
        int c = T & 1023;
        int h = c >> 6;
        int ep = c & 63;
        const float* b = (f == 0) ? bq : (f == 1) ? bk : bv;
        const float* P = (f == 0) ? sw : (f == 1) ? kpw : vlw;
        const float* pb = (f == 0) ? sb : (f == 1) ? kpb : vlb;
        float* O = (f == 0) ? g_bqf : (f == 1) ? g_bkf : g_bvf;
        float sum = pb[ep];
        for (int e = 0; e < DK; e++) sum += b[(h << 6) + e] * P[e * DK + ep];
        O[c] = sum;
        return;
    }
    T -= 3072;
    if (T < 16384) {
        int d = T >> 4, h = T & 15;
        float sum = 0.f;
        for (int e = 0; e < DK; e++) sum += wk[d * DD + (h << 6) + e] * chan_w[e];
        g_wck[d * HH + h] = sum;
        return;
    }
    T -= 16384;
    if (T < 16384) {
        int d = T >> 4, h = T & 15;
        float sum = 0.f;
        for (int e = 0; e < DK; e++) sum += wk[d * DD + (h << 6) + e] * chan_b[e];
        g_wcb[d * HH + h] = sum;
        return;
    }
    T -= 16384;
    if (T < 16) {
        float sum = 0.f;
        for (int e = 0; e < DK; e++) sum += bk[(T << 6) + e] * chan_w[e];
        g_bck[T] = sum;
        return;
    }
    T -= 16;
    if (T < 16) {
        float sum = 0.f;
        for (int e = 0; e < DK; e++) sum += bk[(T << 6) + e] * chan_b[e];
        g_bcb[T] = sum;
        return;
    }
    T -= 16;
    if (T < 64) {                           // qv scaled x8 (Q stored pre-scaled /8)
        float sum = 0.f;
        for (int ep = 0; ep < DK; ep++) sum += qpw[T * DK + ep];
        g_qv[T] = sum * 0.125f;
        return;
    }
    T -= 64;
    if (T == 0) {
        float sum = 0.f;
        for (int ep = 0; ep < DK; ep++) sum += qpb[ep];
        g_bmean = sum * (1.f / 64.f);
    }
}

// ---------------- 2. fp16 tensor-core GEMM -------------------------------------
// mode 0: f32 out. mode 2: elu+pack. mode 3: transposed-V. mode 4: elu,x1/8,pack.
#define GSTAGES 3
#define GBKP 16
#define ASTP 20
#define BSTP 136
#define ASZP (128 * ASTP)
#define BSZP (GBKP * BSTP)
#define GSM_BYTES (GSTAGES * (ASZP + BSZP) * 4)   // 56832

struct GemmArgs {
    const uint32_t* A[3];
    const uint32_t* B[3];
    const float* bias[3];
    void* C[3];
    int mode[3];
    int Nn[3];
};

__device__ __forceinline__ void gemm_load_stage(uint32_t* As, uint32_t* Bs,
                                                const uint32_t* A, const uint32_t* Bm,
                                                int brow, int bcol, int kt, int tid,
                                                int Nn) {
#pragma unroll
    for (int l = 0; l < 2; l++) {
        int lin = tid + l * 256;
        int row = lin >> 2, c4 = (lin & 3) << 2;
        cpa16(&As[row * ASTP + c4], &A[(size_t)(brow + row) * (DD / 2) + kt * GBKP + c4]);
    }
#pragma unroll
    for (int l = 0; l < 2; l++) {
        int lin = tid + l * 256;
        int kr = lin >> 5, c4 = (lin & 31) << 2;
        cpa16(&Bs[kr * BSTP + c4], &Bm[(size_t)(kt * GBKP + kr) * Nn + bcol + c4]);
    }
}

__global__ void __launch_bounds__(256, 2)
gemm_f16(GemmArgs ga) {
    extern __shared__ uint32_t smem_u[];
    uint32_t* Asm = smem_u;
    uint32_t* Bsm = smem_u + GSTAGES * ASZP;

    int z = blockIdx.z;
    const uint32_t* A = ga.A[z];
    const uint32_t* Bm = ga.B[z];
    const float* bias = ga.bias[z];
    int mode = ga.mode[z];
    int Nn = ga.Nn[z];

    int tid = threadIdx.x;
    int brow, bcol;
    if (mode == 3) { brow = blockIdx.x * 128; bcol = blockIdx.y * 128; }
    else           { brow = blockIdx.y * 128; bcol = blockIdx.x * 128; }
    int warp = tid >> 5;
    int lane = tid & 31;
    int gr = lane >> 2;
    int gc = lane & 3;
    int wrow = (warp >> 2) * 64;
    int wcol = (warp & 3) * 32;

    float acc[4][4][4];
#pragma unroll
    for (int mt = 0; mt < 4; mt++)
#pragma unroll
        for (int nt = 0; nt < 4; nt++)
#pragma unroll
            for (int r = 0; r < 4; r++) acc[mt][nt][r] = 0.f;

    const int KT = (DD / 2) / GBKP;   // 32
    gemm_load_stage(Asm, Bsm, A, Bm, brow, bcol, 0, tid, Nn);
    asm volatile("cp.async.commit_group;\n");
    gemm_load_stage(Asm + ASZP, Bsm + BSZP, A, Bm, brow, bcol, 1, tid, Nn);
    asm volatile("cp.async.commit_group;\n");

    int s0 = 0, s1 = 1, s2 = 2;
    for (int kt = 0; kt < KT; kt++) {
        asm volatile("cp.async.wait_group 1;\n" ::: "memory");
        __syncthreads();
        uint32_t* As = Asm + s0 * ASZP;
        uint32_t* Bs = Bsm + s0 * BSZP;
#pragma unroll
        for (int c2 = 0; c2 < 2; c2++) {
            int kpb = c2 * 8;
            uint32_t af[4][4], bf[4][2];
#pragma unroll
            for (int mt = 0; mt < 4; mt++) {
                int row0 = wrow + mt * 16 + gr;
                af[mt][0] = As[row0 * ASTP + kpb + gc];
                af[mt][1] = As[(row0 + 8) * ASTP + kpb + gc];
                af[mt][2] = As[row0 * ASTP + kpb + gc + 4];
                af[mt][3] = As[(row0 + 8) * ASTP + kpb + gc + 4];
            }
#pragma unroll
            for (int nt = 0; nt < 4; nt++) {
                int col0 = wcol + nt * 8 + gr;
                bf[nt][0] = Bs[(kpb + gc) * BSTP + col0];
                bf[nt][1] = Bs[(kpb + gc + 4) * BSTP + col0];
            }
#pragma unroll
            for (int mt = 0; mt < 4; mt++)
#pragma unroll
                for (int nt = 0; nt < 4; nt++)
                    MMA_F16(acc[mt][nt], af[mt], bf[nt]);
        }
        int nk = kt + 2;
        if (nk < KT)
            gemm_load_stage(Asm + s2 * ASZP, Bsm + s2 * BSZP, A, Bm, brow, bcol, nk, tid, Nn);
        asm volatile("cp.async.commit_group;\n");
        int t = s0; s0 = s1; s1 = s2; s2 = t;
    }

    // epilogue
#pragma unroll
    for (int mt = 0; mt < 4; mt++) {
        int r0 = brow + wrow + mt * 16 + gr;
#pragma unroll
        for (int nt = 0; nt < 4; nt++) {
            int c0 = bcol + wcol + nt * 8 + (gc << 1);
            float v0, v1, v2, v3;
            if (mode == 3) {
                float rb0 = bias[r0], rb1 = bias[r0 + 8];
                v0 = acc[mt][nt][0] + rb0;
                v1 = acc[mt][nt][1] + rb0;
                v2 = acc[mt][nt][2] + rb1;
                v3 = acc[mt][nt][3] + rb1;
            } else {
                float b0 = bias[c0], b1 = bias[c0 + 1];
                v0 = acc[mt][nt][0] + b0;
                v1 = acc[mt][nt][1] + b1;
                v2 = acc[mt][nt][2] + b0;
                v3 = acc[mt][nt][3] + b1;
            }
            if (mode >= 2) {
                v0 = v0 > 0.f ? v0 : (__expf(v0) - 1.f);
                v1 = v1 > 0.f ? v1 : (__expf(v1) - 1.f);
                v2 = v2 > 0.f ? v2 : (__expf(v2) - 1.f);
                v3 = v3 > 0.f ? v3 : (__expf(v3) - 1.f);
            }
            if (mode == 4) {
                v0 *= 0.125f; v1 *= 0.125f; v2 *= 0.125f; v3 *= 0.125f;
            }
            if (mode == 3) {
                uint32_t* Cw = (uint32_t*)ga.C[z];
                Cw[(size_t)r0 * (MM / 2) + (c0 >> 1)] = packh2(v0, v1);
                Cw[(size_t)(r0 + 8) * (MM / 2) + (c0 >> 1)] = packh2(v2, v3);
            } else if (mode >= 2) {
                uint32_t* Cw = (uint32_t*)ga.C[z];
                Cw[(size_t)r0 * (DD / 2) + (c0 >> 1)] = packh2(v0, v1);
                Cw[(size_t)(r0 + 8) * (DD / 2) + (c0 >> 1)] = packh2(v2, v3);
            } else {
                float* Cf = (float*)ga.C[z];
                *(float2*)&Cf[(size_t)r0 * DD + c0] = make_float2(v0, v1);
                *(float2*)&Cf[(size_t)(r0 + 8) * DD + c0] = make_float2(v2, v3);
            }
        }
    }
}

// ---------------- 3. ck/cb skinny GEMV (writes fp16 head-major) -----------------
__global__ void ckcb_kernel(const float* __restrict__ key) {
    __shared__ float rows[8][1024];
    int tid = threadIdx.x;
    int row0 = blockIdx.x * 8;
#pragma unroll
    for (int l = 0; l < 8; l++) {
        int lin = tid + l * 256;
        int r = lin >> 8;
        int c4 = (lin & 255) << 2;
        *(float4*)&rows[r][c4] = *(const float4*)&key[(size_t)(row0 + r) * DD + c4];
    }
    __syncthreads();
    int r = tid >> 5;
    int o = tid & 31;
    int h = o & 15;
    int isB = o >> 4;
    const float* wp = isB ? g_wcb : g_wck;
    float sum = isB ? g_bcb[h] : g_bck[h];
#pragma unroll 8
    for (int d = 0; d < DD; d++) sum += rows[r][d] * wp[d * HH + h];
    (isB ? g_cbh : g_ckh)[(size_t)h * MM + row0 + r] = __float2half(sum);
}

// ---------------- 4. flash attention: register-resident P, occ 3 ---------------
// CTA: 64 q-rows x (b,h). 4 warps x 16 q-rows. K-tiles of 64, 2-buffer cp.async.
// KEY IDENTITY: QK^T C-fragment (rows gr/gr+8, keys nf*8+2gc,+1) on thread
// (gr,gc) is EXACTLY the PV A-fragment (chunk c uses nf=2c and nf=2c+1).
// P never touches smem: packed p-words stay in registers.
#define AKS 36
#define TILE_U (64 * AKS)
#define ASM_BYTES ((5 * TILE_U + 128) * 4)   // 46592

__global__ void __launch_bounds__(128, 3) attn_tc_kernel() {
    extern __shared__ uint32_t smu[];
    uint32_t* Qh  = smu;                    // Q [q][ep]
    uint32_t* KsB = smu + TILE_U;           // 2 x K [key][ep]
    uint32_t* VtB = smu + 3 * TILE_U;       // 2 x V^T [e][kp]
    uint32_t* ckB = smu + 5 * TILE_U;       // 2 x 32 u32 (64 fp16 ck)
    uint32_t* cbB = ckB + 64;               // 2 x 32 u32 (64 fp16 cb)

    int tid = threadIdx.x;
    int q0 = blockIdx.x * 64;
    int h = blockIdx.y;
    int b = blockIdx.z;
    int warp = tid >> 5;
    int lane = tid & 31;
    int gr = lane >> 2;
    int gc = lane & 3;
    int wrow = warp * 16;

    // issue Q staging (group 0)
#pragma unroll
    for (int l = 0; l < 4; l++) {
        int lin = tid + l * 128;
        int r = lin >> 3;
        int c4 = (lin & 7) << 2;
        cpa16(&Qh[r * AKS + c4],
              &g_qs[(size_t)((b << 10) + q0 + r) * (DD / 2) + (h << 5) + c4]);
    }
    asm volatile("cp.async.commit_group;\n");

    auto issue_tile = [&](int kt, int buf) {
        int k0 = kt * 64;
        uint32_t* Ks = KsB + buf * TILE_U;
        uint32_t* Vt = VtB + buf * TILE_U;
#pragma unroll
        for (int l = 0; l < 4; l++) {
            int lin = tid + l * 128;
            int r = lin >> 3;
            int c4 = (lin & 7) << 2;
            cpa16(&Ks[r * AKS + c4],
                  &g_k2[(size_t)((b << 10) + k0 + r) * (DD / 2) + (h << 5) + c4]);
            cpa16(&Vt[r * AKS + c4],
                  &g_v2t[(size_t)((h << 6) + r) * (MM / 2) + (((b << 10) + k0) >> 1) + c4]);
        }
        if (tid < 8)
            cpa16(&ckB[buf * 32 + tid * 4], &g_ckh[(size_t)h * MM + (b << 10) + k0 + tid * 8]);
        else if (tid < 16)
            cpa16(&cbB[buf * 32 + (tid - 8) * 4],
                  &g_cbh[(size_t)h * MM + (b << 10) + k0 + (tid - 8) * 8]);
        asm volatile("cp.async.commit_group;\n");
    };
    issue_tile(0, 0);

    asm volatile("cp.async.wait_group 1;\n" ::: "memory");
    __syncthreads();

    // Q fragments
    uint32_t qf[4][4];
#pragma unroll
    for (int c = 0; c < 4; c++) {
        qf[c][0] = Qh[(wrow + gr) * AKS + c * 8 + gc];
        qf[c][1] = Qh[(wrow + gr + 8) * AKS + c * 8 + gc];
        qf[c][2] = Qh[(wrow + gr) * AKS + c * 8 + gc + 4];
        qf[c][3] = Qh[(wrow + gr + 8) * AKS + c * 8 + gc + 4];
    }
    // inline per-row gate scalar m = Q_row . qv + bmean  (qv pre-scaled x8)
    const __half* q0h = (const __half*)(Qh + (wrow + gr) * AKS);
    const __half* q1h = (const __half*)(Qh + (wrow + gr + 8) * AKS);
    float a0 = 0.f, a1 = 0.f;
#pragma unroll
    for (int e16 = 0; e16 < 16; e16++) {
        int e = gc * 16 + e16;
        float qv = __ldg(&g_qv[e]);
        a0 = fmaf(__half2float(q0h[e]), qv, a0);
        a1 = fmaf(__half2float(q1h[e]), qv, a1);
    }
#pragma unroll
    for (int d = 1; d < 4; d <<= 1) {
        a0 += __shfl_xor_sync(0xffffffffu, a0, d);
        a1 += __shfl_xor_sync(0xffffffffu, a1, d);
    }
    float bmean = g_bmean;
    __half2 mq0h2 = __float2half2_rn(a0 + bmean);
    __half2 mq1h2 = __float2half2_rn(a1 + bmean);
    const __half2 nlog2e = __float2half2_rn(-1.44269504f);
    const __half2 oneh2 = __float2half2_rn(1.f);

    int qrow0 = q0 + wrow + gr;
    int qrow1 = qrow0 + 8;
    float rm0 = -INFINITY, rm1 = -INFINITY, rs0 = 0.f, rs1 = 0.f;
    float ofr[8][4];
#pragma unroll
    for (int nf = 0; nf < 8; nf++)
#pragma unroll
        for (int r = 0; r < 4; r++) ofr[nf][r] = 0.f;

    unsigned pmbase0 = ((unsigned)((b << 10) + qrow0)) << 5;
    unsigned pmbase1 = ((unsigned)((b << 10) + qrow1)) << 5;

    for (int kt = 0; kt < 16; kt++) {
        int cur = kt & 1;
        __syncthreads();
        if (kt < 15) issue_tile(kt + 1, 1 - cur);
        if (kt < 15) { asm volatile("cp.async.wait_group 1;\n" ::: "memory"); }
        else         { asm volatile("cp.async.wait_group 0;\n" ::: "memory"); }
        __syncthreads();

        uint32_t* Ks = KsB + cur * TILE_U;
        uint32_t* Vt = VtB + cur * TILE_U;
        const __half2* ckh = (const __half2*)(ckB + cur * 32);
        const __half2* cbh = (const __half2*)(cbB + cur * 32);
        int k0 = kt * 64;

        // ---- scores S = Q @ K^T (fp16; Q pre-scaled by 1/8) ----
        float sfr[8][4];
#pragma unroll
        for (int nf = 0; nf < 8; nf++)
#pragma unroll
            for (int r = 0; r < 4; r++) sfr[nf][r] = 0.f;
#pragma unroll
        for (int c = 0; c < 4; c++) {
#pragma unroll
            for (int nf = 0; nf < 8; nf++) {
                uint32_t bf[2];
                bf[0] = Ks[(nf * 8 + gr) * AKS + c * 8 + gc];
                bf[1] = Ks[(nf * 8 + gr) * AKS + c * 8 + gc + 4];
                MMA_F16(sfr[nf], qf[c], bf);
            }
        }

        // ---- gate (f16x2 sigmoid) + mask ----
        unsigned w00 = g_pm[pmbase0 + (k0 >> 5)];
        unsigned w01 = g_pm[pmbase0 + (k0 >> 5) + 1];
        unsigned w10 = g_pm[pmbase1 + (k0 >> 5)];
        unsigned w11 = g_pm[pmbase1 + (k0 >> 5) + 1];
#pragma unroll
        for (int nf = 0; nf < 8; nf++) {
            int c0 = nf * 8 + (gc << 1);
            int c1 = c0 + 1;
            __half2 ckp = ckh[nf * 4 + gc];
            __half2 cbp = cbh[nf * 4 + gc];
            __half2 l0 = __hfma2(mq0h2, ckp, cbp);
            __half2 l1 = __hfma2(mq1h2, ckp, cbp);
            __half2 g0h = h2rcp(__hadd2(oneh2, h2exp2(__hmul2(l0, nlog2e))));
            __half2 g1h = h2rcp(__hadd2(oneh2, h2exp2(__hmul2(l1, nlog2e))));
            float2 gf0 = __half22float2(g0h);
            float2 gf1 = __half22float2(g1h);
            float v0 = sfr[nf][0] * gf0.x;
            float v1 = sfr[nf][1] * gf0.y;
            float v2 = sfr[nf][2] * gf1.x;
            float v3 = sfr[nf][3] * gf1.y;
            unsigned wa0 = (c0 < 32) ? w00 : w01;
            unsigned wa1 = (c1 < 32) ? w00 : w01;
            unsigned wb0 = (c0 < 32) ? w10 : w11;
            unsigned wb1 = (c1 < 32) ? w10 : w11;
            if (!((wa0 >> (c0 & 31)) & 1u)) v0 = -1e9f;
            if (!((wa1 >> (c1 & 31)) & 1u)) v1 = -1e9f;
            if (!((wb0 >> (c0 & 31)) & 1u)) v2 = -1e9f;
            if (!((wb1 >> (c1 & 31)) & 1u)) v3 = -1e9f;
            sfr[nf][0] = v0; sfr[nf][1] = v1; sfr[nf][2] = v2; sfr[nf][3] = v3;
        }

        // ---- online softmax ----
        float m0 = -INFINITY, m1 = -INFINITY;
#pragma unroll
        for (int nf = 0; nf < 8; nf++) {
            m0 = fmaxf(m0, fmaxf(sfr[nf][0], sfr[nf][1]));
            m1 = fmaxf(m1, fmaxf(sfr[nf][2], sfr[nf][3]));
        }
#pragma unroll
        for (int d = 1; d < 4; d <<= 1) {
            m0 = fmaxf(m0, __shfl_xor_sync(0xffffffffu, m0, d));
            m1 = fmaxf(m1, __shfl_xor_sync(0xffffffffu, m1, d));
        }
        float tm0 = fmaxf(rm0, m0);
        float tm1 = fmaxf(rm1, m1);
        float sc0 = __expf(rm0 - tm0);
        float sc1 = __expf(rm1 - tm1);
        rm0 = tm0; rm1 = tm1;
        float sum0 = 0.f, sum1 = 0.f;
#pragma unroll
        for (int nf = 0; nf < 8; nf++) {
            float p0 = __expf(sfr[nf][0] - tm0);
            float p1 = __expf(sfr[nf][1] - tm0);
            float p2 = __expf(sfr[nf][2] - tm1);
            float p3 = __expf(sfr[nf][3] - tm1);
            sum0 += p0 + p1;
            sum1 += p2 + p3;
            sfr[nf][0] = p0; sfr[nf][1] = p1; sfr[nf][2] = p2; sfr[nf][3] = p3;
        }
#pragma unroll
        for (int d = 1; d < 4; d <<= 1) {
            sum0 += __shfl_xor_sync(0xffffffffu, sum0, d);
            sum1 += __shfl_xor_sync(0xffffffffu, sum1, d);
        }
        rs0 = rs0 * sc0 + sum0;
        rs1 = rs1 * sc1 + sum1;
#pragma unroll
        for (int nf = 0; nf < 8; nf++) {
            ofr[nf][0] *= sc0; ofr[nf][1] *= sc0;
            ofr[nf][2] *= sc1; ofr[nf][3] *= sc1;
        }

        // ---- pack P in registers (fragment identity; NO smem round trip) ----
        uint32_t pw0[8], pw1[8];
#pragma unroll
        for (int nf = 0; nf < 8; nf++) {
            pw0[nf] = packh2(sfr[nf][0], sfr[nf][1]);   // rows gr,   keys 8nf+2gc,+1
            pw1[nf] = packh2(sfr[nf][2], sfr[nf][3]);   // rows gr+8, same keys
        }

        // ---- O += P @ V (fp16; V^T [e][kp]); A-fragment straight from regs ----
#pragma unroll
        for (int c = 0; c < 4; c++) {
            uint32_t af[4];
            af[0] = pw0[2 * c];          // row gr,   keys 16c+2gc,+1
            af[1] = pw1[2 * c];          // row gr+8, keys 16c+2gc,+1
            af[2] = pw0[2 * c + 1];      // row gr,   keys 16c+8+2gc,+1
            af[3] = pw1[2 * c + 1];      // row gr+8, keys 16c+8+2gc,+1
#pragma unroll
            for (int nf = 0; nf < 8; nf++) {
                uint32_t bf[2];
                bf[0] = Vt[(nf * 8 + gr) * AKS + c * 8 + gc];
                bf[1] = Vt[(nf * 8 + gr) * AKS + c * 8 + gc + 4];
                MMA_F16(ofr[nf], af, bf);
            }
        }
    }

    // ---- normalize + write fp16-packed ----
    float inv0 = 1.f / rs0;
    float inv1 = 1.f / rs1;
#pragma unroll
    for (int nf = 0; nf < 8; nf++) {
        int c0 = (h << 6) + nf * 8 + (gc << 1);
        g_xp[(size_t)((b << 10) + qrow0) * (DD / 2) + (c0 >> 1)] =
            packh2(ofr[nf][0] * inv0, ofr[nf][1] * inv0);
        g_xp[(size_t)((b << 10) + qrow1) * (DD / 2) + (c0 >> 1)] =
            packh2(ofr[nf][2] * inv1, ofr[nf][3] * inv1);
    }
}

// ---------------- launch --------------------------------------------------------
extern "C" void kernel_launch(void* const* d_in, const int* in_sizes, int n_in,
                              void* d_out, int out_size) {
    const float* query = (const float*)d_in[0];
    const float* key   = (const float*)d_in[1];
    const float* value = (const float*)d_in[2];
    const int*   mask  = (const int*)d_in[3];
    const float* wq = (const float*)d_in[4];
    const float* bq = (const float*)d_in[5];
    const float* wk = (const float*)d_in[6];
    const float* bk = (const float*)d_in[7];
    const float* wv = (const float*)d_in[8];
    const float* bv = (const float*)d_in[9];
    const float* wo = (const float*)d_in[10];
    const float* bo = (const float*)d_in[11];
    const float* spatial_w = (const float*)d_in[12];
    const float* spatial_b = (const float*)d_in[13];
    const float* qproj_w = (const float*)d_in[14];
    const float* qproj_b = (const float*)d_in[15];
    const float* kproj_w = (const float*)d_in[16];
    const float* kproj_b = (const float*)d_in[17];
    const float* vlin_w = (const float*)d_in[18];
    const float* vlin_b = (const float*)d_in[19];
    const float* chan_w = (const float*)d_in[20];
    const float* chan_b = (const float*)d_in[21];
    float* out = (float*)d_out;

    float *p_bqf, *p_bkf, *p_bvf;
    uint32_t *p_wqp, *p_wkp, *p_wvt, *p_wop, *p_aq, *p_ak, *p_avt;
    uint32_t *p_qs, *p_k2, *p_v2t, *p_xp;
    cudaGetSymbolAddress((void**)&p_bqf, g_bqf);
    cudaGetSymbolAddress((void**)&p_bkf, g_bkf);
    cudaGetSymbolAddress((void**)&p_bvf, g_bvf);
    cudaGetSymbolAddress((void**)&p_wqp, g_wqp);
    cudaGetSymbolAddress((void**)&p_wkp, g_wkp);
    cudaGetSymbolAddress((void**)&p_wvt, g_wvt);
    cudaGetSymbolAddress((void**)&p_wop, g_wop);
    cudaGetSymbolAddress((void**)&p_aq, g_aq);
    cudaGetSymbolAddress((void**)&p_ak, g_ak);
    cudaGetSymbolAddress((void**)&p_avt, g_avt);
    cudaGetSymbolAddress((void**)&p_qs, g_qs);
    cudaGetSymbolAddress((void**)&p_k2, g_k2);
    cudaGetSymbolAddress((void**)&p_v2t, g_v2t);
    cudaGetSymbolAddress((void**)&p_xp, g_xp);

    cudaFuncSetAttribute(gemm_f16, cudaFuncAttributeMaxDynamicSharedMemorySize, GSM_BYTES);
    cudaFuncSetAttribute(attn_tc_kernel, cudaFuncAttributeMaxDynamicSharedMemorySize, ASM_BYTES);

    // 1. all independent prep in one launch
    mega_prep<<<20621, 256>>>(query, key, value, mask,
                              wq, bq, wk, bk, wv, bv, wo,
                              spatial_w, spatial_b, qproj_w, qproj_b,
                              kproj_w, kproj_b, vlin_w, vlin_b, chan_w, chan_b);
    // 2. ck/cb gate scalars (fp16, head-major)
    ckcb_kernel<<<MM / 8, 256>>>(key);

    // 3. merged QKV fp16 GEMM: Q (elu, x1/8), K (elu), V transposed (elu)
    GemmArgs gqkv;
    gqkv.A[0] = p_aq;  gqkv.A[1] = p_ak;  gqkv.A[2] = p_wvt;
    gqkv.B[0] = p_wqp; gqkv.B[1] = p_wkp; gqkv.B[2] = p_avt;
    gqkv.bias[0] = p_bqf; gqkv.bias[1] = p_bkf; gqkv.bias[2] = p_bvf;
    gqkv.C[0] = p_qs;  gqkv.C[1] = p_k2;  gqkv.C[2] = p_v2t;
    gqkv.mode[0] = 4;  gqkv.mode[1] = 2;  gqkv.mode[2] = 3;
    gqkv.Nn[0] = DD;   gqkv.Nn[1] = DD;   gqkv.Nn[2] = MM;
    gemm_f16<<<dim3(8, 32, 3), 256, GSM_BYTES>>>(gqkv);

    // 4. attention: register-P fp16 MMA (occ 3, cp.async)
    attn_tc_kernel<<<dim3(SS / 64, HH, BB), 128, ASM_BYTES>>>();

    // 5. fp16 output projection
    GemmArgs go;
    go.A[0] = go.A[1] = go.A[2] = p_xp;
    go.B[0] = go.B[1] = go.B[2] = p_wop;
    go.bias[0] = go.bias[1] = go.bias[2] = bo;
    go.C[0] = go.C[1] = go.C[2] = out;
    go.mode[0] = go.mode[1] = go.mode[2] = 0;
    go.Nn[0] = go.Nn[1] = go.Nn[2] = DD;
    gemm_f16<<<dim3(8, 32, 1), 256, GSM_BYTES>>>(go);
}